// round 14
// baseline (speedup 1.0000x reference)
#include <cuda_runtime.h>
#include <cstdint>
#include <mma.h>
using namespace nvcuda;

#define NS 512
#define NR 384
#define CM 256
#define MT (NR*32)       // 12288
#define RT (NR*NR)       // 147456

__device__ float g_L[(size_t)NS * MT];
__device__ float g_R[(size_t)NS * MT];
__device__ float g_Wt[1024 * 128];
__device__ float g_rinv[RT];

__device__ __forceinline__ void cp16(uint32_t dst, const float* src) {
    asm volatile("cp.async.cg.shared.global [%0], [%1], 16;\n" :: "r"(dst), "l"(src));
}
__device__ __forceinline__ void cp_commit() {
    asm volatile("cp.async.commit_group;\n" ::);
}
__device__ __forceinline__ void cp_wait1() {
    asm volatile("cp.async.wait_group 1;\n" ::);
}

// ---------------- Kernel 1: LN + left/right projection (fp32 exact) --------
// Epilogue stores tf32-rounded values so the GEMM hot loop needs no cvt.
__global__ __launch_bounds__(256) void ln_proj_kernel(
    const float* __restrict__ act, const float* __restrict__ mask,
    const float* __restrict__ gamma, const float* __restrict__ beta,
    const float* __restrict__ lw, const float* __restrict__ lb,
    const float* __restrict__ rw, const float* __restrict__ rb)
{
    extern __shared__ float sm[];
    float* xs    = sm;                 // [64][260]
    float* sW    = sm + 64 * 260;      // [256][64]
    float* smask = sW + 256 * 64;      // [64]
    const int tid  = threadIdx.x;
    const int warp = tid >> 5, lane = tid & 31;
    const int rbase = blockIdx.x * 64;

    for (int i = 0; i < 64; i++) {
        int idx = tid + i * 256;
        int k = idx >> 6, cc = idx & 63;
        sW[idx] = (cc < 32) ? lw[k * 32 + cc] : rw[k * 32 + (cc - 32)];
    }
    for (int rr = 0; rr < 8; rr++) {
        int lr = warp * 8 + rr;
        int r  = rbase + lr;
        const float* arow = act + (size_t)r * CM;
        float x[8], s = 0.f, s2 = 0.f;
        #pragma unroll
        for (int j = 0; j < 8; j++) { x[j] = arow[lane + 32 * j]; s += x[j]; s2 += x[j] * x[j]; }
        #pragma unroll
        for (int o = 16; o > 0; o >>= 1) {
            s  += __shfl_xor_sync(0xffffffffu, s,  o);
            s2 += __shfl_xor_sync(0xffffffffu, s2, o);
        }
        float mu = s * (1.f / 256.f);
        float rstd = rsqrtf(s2 * (1.f / 256.f) - mu * mu + 1e-5f);
        float m = mask[r];
        if (lane == 0) smask[lr] = m;
        #pragma unroll
        for (int j = 0; j < 8; j++) {
            int k = lane + 32 * j;
            xs[lr * 260 + k] = ((x[j] - mu) * rstd * gamma[k] + beta[k]) * m;
        }
    }
    __syncthreads();

    const int tr4 = (tid >> 4) * 4, tc4 = (tid & 15) * 4;
    float acc[4][4] = {};
    for (int k = 0; k < 256; k += 4) {
        float4 w0 = *(const float4*)(sW + (k + 0) * 64 + tc4);
        float4 w1 = *(const float4*)(sW + (k + 1) * 64 + tc4);
        float4 w2 = *(const float4*)(sW + (k + 2) * 64 + tc4);
        float4 w3 = *(const float4*)(sW + (k + 3) * 64 + tc4);
        #pragma unroll
        for (int i = 0; i < 4; i++) {
            float4 xv = *(const float4*)(xs + (tr4 + i) * 260 + k);
            acc[i][0] += xv.x * w0.x + xv.y * w1.x + xv.z * w2.x + xv.w * w3.x;
            acc[i][1] += xv.x * w0.y + xv.y * w1.y + xv.z * w2.y + xv.w * w3.y;
            acc[i][2] += xv.x * w0.z + xv.y * w1.z + xv.z * w2.z + xv.w * w3.z;
            acc[i][3] += xv.x * w0.w + xv.y * w1.w + xv.z * w2.w + xv.w * w3.w;
        }
    }
    float b0, b1, b2, b3;
    if (tc4 < 32) { b0 = lb[tc4]; b1 = lb[tc4+1]; b2 = lb[tc4+2]; b3 = lb[tc4+3]; }
    else { b0 = rb[tc4-32]; b1 = rb[tc4-31]; b2 = rb[tc4-30]; b3 = rb[tc4-29]; }
    #pragma unroll
    for (int i = 0; i < 4; i++) {
        int r = rbase + tr4 + i;
        int aa = r / NR, bb = r % NR;
        float m = smask[tr4 + i];
        float4 o;
        o.x = wmma::__float_to_tf32(acc[i][0] + m * b0);
        o.y = wmma::__float_to_tf32(acc[i][1] + m * b1);
        o.z = wmma::__float_to_tf32(acc[i][2] + m * b2);
        o.w = wmma::__float_to_tf32(acc[i][3] + m * b3);
        if (tc4 < 32) *(float4*)(g_L + (size_t)aa * MT + bb * 32 + tc4) = o;
        else          *(float4*)(g_R + (size_t)aa * MT + bb * 32 + (tc4 - 32)) = o;
    }
}

// ---------------- Kernel 2: rinv = 1/(eps + mask^T mask) -------------------
__global__ __launch_bounds__(NR) void norm_kernel(const float* __restrict__ mask)
{
    int b = blockIdx.x, d = threadIdx.x;
    float s = 0.f;
    for (int a = 0; a < NS; a++) s += mask[a * NR + b] * mask[a * NR + d];
    g_rinv[b * NR + d] = 1.f / (1e-3f + s);
}

// ---------------- Kernel 2b: pre-truncate output_w to tf32 -----------------
__global__ __launch_bounds__(512) void trunc_w_kernel(const float* __restrict__ ow)
{
    int i = blockIdx.x * 512 + threadIdx.x;     // 131072 elems, grid 256
    g_Wt[i] = wmma::__float_to_tf32(ow[i]);
}

// ---- pipelined stage loaders (512 threads) --------------------------------
__device__ __forceinline__ void load_stage_LR(uint32_t smb, int tid, int ks, int s,
                                              int m0, int n0)
{
    uint32_t aA = smb + (uint32_t)s * 12544u * 4u;
    uint32_t aB = aA + 32u * 132u * 4u;
    int k0 = ks * 32;
    #pragma unroll
    for (int i = 0; i < 2; i++) {
        int idx = tid + i * 512;                    // 1024 float4s (A)
        int kk = idx >> 5, c4 = (idx & 31) << 2;
        cp16(aA + (uint32_t)(kk * 132 + c4) * 4u,
             g_L + (size_t)(k0 + kk) * MT + m0 + c4);
    }
    #pragma unroll
    for (int i = 0; i < 4; i++) {
        int idx = tid + i * 512;                    // 2048 float4s (B)
        int kk = idx >> 6, c4 = (idx & 63) << 2;
        cp16(aB + (uint32_t)(kk * 260 + c4) * 4u,
             g_R + (size_t)(k0 + kk) * MT + n0 + c4);
    }
}

// W staging: stage s holds chunks {i, 16+i} (one per K-group), 2*4224 floats
__device__ __forceinline__ void load_stage_W2(uint32_t smb, int tid, int i_next, int s)
{
    uint32_t aW = smb + (33024u + (uint32_t)s * 8448u) * 4u;
    #pragma unroll
    for (int g = 0; g < 2; g++) {
        int k0 = (g * 16 + i_next) * 32;
        #pragma unroll
        for (int i = 0; i < 2; i++) {
            int idx = tid + i * 512;                // 1024 float4s per chunk
            int kk = idx >> 5, f4 = (idx & 31) << 2;
            cp16(aW + (uint32_t)(g * 4224 + kk * 132 + f4) * 4u,
                 g_Wt + (size_t)(k0 + kk) * 128 + f4);
        }
    }
}

// ---------------- Kernel 3: FUSED  inter = L^T R ;  out = rinv*(inter@W)+ob
// 512 threads. Mainloop: 4x4 warp grid, 32x64 per warp, K=512.
// Phase 2: 2-way K-split (warps 0-7 chunks 0-15, warps 8-15 chunks 16-31).
// smem (floats): phase1: stage s at s*12544: sA[32][132] + sB[32][260]
//                phase2: sI[32][1032] at 0; W stages at 33024 + s*8448
//                epilogue partials: sO[g] at 33024 + g*4224
__global__ __launch_bounds__(512) void gemm_fused_kernel(
    const float* __restrict__ ob, float* __restrict__ out)
{
    extern __shared__ float sm[];
    const int tid  = threadIdx.x;
    const int warp = tid >> 5;
    const int wm = warp >> 2, wn = warp & 3;     // 4x4 warp grid
    const int m0 = blockIdx.y * 128, n0 = blockIdx.x * 256;
    const uint32_t smb = (uint32_t)__cvta_generic_to_shared(sm);

    wmma::fragment<wmma::accumulator, 16, 16, 8, float> c[2][4];
    #pragma unroll
    for (int i = 0; i < 2; i++)
        #pragma unroll
        for (int j = 0; j < 4; j++) wmma::fill_fragment(c[i][j], 0.0f);

    // ---- mainloop: double-buffered cp.async, 16 k-chunks of 32 ----
    load_stage_LR(smb, tid, 0, 0, m0, n0);
    cp_commit();
    for (int ks = 0; ks < 16; ks++) {
        int s = ks & 1;
        if (ks + 1 < 16) load_stage_LR(smb, tid, ks + 1, s ^ 1, m0, n0);
        cp_commit();
        cp_wait1();
        __syncthreads();
        float* sA = sm + s * 12544;
        float* sB = sA + 4224;
        #pragma unroll
        for (int kk = 0; kk < 32; kk += 8) {
            wmma::fragment<wmma::matrix_a, 16, 16, 8, wmma::precision::tf32, wmma::col_major> af[2];
            wmma::fragment<wmma::matrix_b, 16, 16, 8, wmma::precision::tf32, wmma::row_major> bf[4];
            #pragma unroll
            for (int i = 0; i < 2; i++)
                wmma::load_matrix_sync(af[i], sA + kk * 132 + wm * 32 + i * 16, 132);
            #pragma unroll
            for (int j = 0; j < 4; j++)
                wmma::load_matrix_sync(bf[j], sB + kk * 260 + wn * 64 + j * 16, 260);
            #pragma unroll
            for (int i = 0; i < 2; i++)
                #pragma unroll
                for (int j = 0; j < 4; j++)
                    wmma::mma_sync(c[i][j], af[i], bf[j], c[i][j]);
        }
        __syncthreads();
    }

    // ---- reorganize: fragment tiles -> sI[r=(b_l*8+d_l)][k=(c*32+e)] ------
    float* sI = sm;            // 32 x 1032
    #pragma unroll
    for (int i = 0; i < 2; i++)
        #pragma unroll
        for (int j = 0; j < 4; j++) {
            int ml = wm * 32 + i * 16, nl = wn * 64 + j * 16;
            int r = (ml >> 5) * 8 + (nl >> 5);
            wmma::store_matrix_sync(sI + (size_t)r * 1032 + (ml & 31) * 32 + (nl & 31),
                                    c[i][j], 32, wmma::mem_row_major);
        }
    __syncthreads();

    // in-place tf32 truncation of sI (once; hot loop below has no cvt)
    #pragma unroll
    for (int i = 0; i < 16; i++) {
        int idx = tid + i * 512;               // 8192 float4s = 32x1024
        int r = idx >> 8, k4 = (idx & 255) << 2;
        float4 v = *(float4*)(sI + r * 1032 + k4);
        v.x = wmma::__float_to_tf32(v.x); v.y = wmma::__float_to_tf32(v.y);
        v.z = wmma::__float_to_tf32(v.z); v.w = wmma::__float_to_tf32(v.w);
        *(float4*)(sI + r * 1032 + k4) = v;
    }
    __syncthreads();

    // ---- fused W-contraction, 2-way K-split: [32 x 1024] @ [1024 x 128] ---
    const int kg = warp >> 3;          // K group 0/1
    const int ws = warp & 7;
    const int pm = ws >> 2, pn = ws & 3;   // 2x4 grid over 32 rows x 128 cols

    wmma::fragment<wmma::accumulator, 16, 16, 8, float> o[2];
    wmma::fill_fragment(o[0], 0.0f);
    wmma::fill_fragment(o[1], 0.0f);

    load_stage_W2(smb, tid, 0, 0);
    cp_commit();
    for (int i = 0; i < 16; i++) {
        int s = i & 1;
        if (i + 1 < 16) load_stage_W2(smb, tid, i + 1, s ^ 1);
        cp_commit();
        cp_wait1();
        __syncthreads();
        float* sWc = sm + 33024 + s * 8448 + kg * 4224;
        int kc = kg * 16 + i;
        #pragma unroll
        for (int kk = 0; kk < 32; kk += 8) {
            wmma::fragment<wmma::matrix_a, 16, 16, 8, wmma::precision::tf32, wmma::row_major> af;
            wmma::load_matrix_sync(af, sI + (pm * 16) * 1032 + kc * 32 + kk, 1032);
            #pragma unroll
            for (int j = 0; j < 2; j++) {
                wmma::fragment<wmma::matrix_b, 16, 16, 8, wmma::precision::tf32, wmma::row_major> bf;
                wmma::load_matrix_sync(bf, sWc + kk * 132 + pn * 32 + j * 16, 132);
                wmma::mma_sync(o[j], af, bf, o[j]);
            }
        }
        __syncthreads();
    }

    // ---- partials -> smem, reduce K-groups, scale by rinv, +bias, store ---
    float* sO = sm + 33024;    // [2][32][132]
    #pragma unroll
    for (int j = 0; j < 2; j++)
        wmma::store_matrix_sync(sO + kg * 4224 + (pm * 16) * 132 + pn * 32 + j * 16,
                                o[j], 132, wmma::mem_row_major);
    __syncthreads();

    const int b0 = blockIdx.y * 4, d0 = blockIdx.x * 8;
    #pragma unroll
    for (int it = 0; it < 2; it++) {
        int flat = tid + it * 512;           // 1024 float4s = 32x128
        int r = flat >> 5, fc = (flat & 31) << 2;
        float4 v0 = *(float4*)(sO + r * 132 + fc);
        float4 v1 = *(float4*)(sO + 4224 + r * 132 + fc);
        int orow  = (b0 + (r >> 3)) * NR + d0 + (r & 7);
        float rv  = g_rinv[orow];
        float4 bb = *(const float4*)(ob + fc);
        float4 w  = { (v0.x + v1.x) * rv + bb.x, (v0.y + v1.y) * rv + bb.y,
                      (v0.z + v1.z) * rv + bb.z, (v0.w + v1.w) * rv + bb.w };
        *(float4*)(out + (size_t)orow * 128 + fc) = w;
    }
}

// ---------------------------------------------------------------------------
extern "C" void kernel_launch(void* const* d_in, const int* in_sizes, int n_in,
                              void* d_out, int out_size)
{
    const float* act      = (const float*)d_in[0];
    const float* mask     = (const float*)d_in[1];
    const float* ln_scale = (const float*)d_in[2];
    const float* ln_off   = (const float*)d_in[3];
    const float* left_w   = (const float*)d_in[4];
    const float* left_b   = (const float*)d_in[5];
    const float* right_w  = (const float*)d_in[6];
    const float* right_b  = (const float*)d_in[7];
    const float* out_w    = (const float*)d_in[8];
    const float* out_b    = (const float*)d_in[9];
    float* out = (float*)d_out;

    const int smem1 = (64 * 260 + 256 * 64 + 64) * 4;       // 132352
    const int smem3 = (33024 + 2 * 8448) * 4;               // 199680
    cudaFuncSetAttribute(ln_proj_kernel,    cudaFuncAttributeMaxDynamicSharedMemorySize, smem1);
    cudaFuncSetAttribute(gemm_fused_kernel, cudaFuncAttributeMaxDynamicSharedMemorySize, smem3);

    ln_proj_kernel<<<(NS * NR) / 64, 256, smem1>>>(act, mask, ln_scale, ln_off,
                                                   left_w, left_b, right_w, right_b);
    norm_kernel<<<NR, NR>>>(mask);
    trunc_w_kernel<<<256, 512>>>(out_w);
    gemm_fused_kernel<<<dim3(MT / 256, MT / 128), 512, smem3>>>(out_b, out);
}

// round 17
// speedup vs baseline: 2.8142x; 2.8142x over previous
#include <cuda_runtime.h>
#include <cuda_fp16.h>
#include <cstdint>
#include <mma.h>
using namespace nvcuda;

#define NS 512
#define NR 384
#define CM 256
#define MT (NR*32)       // 12288
#define RT (NR*NR)       // 147456

__device__ __half g_Lh[(size_t)NS * MT];   // [k][m] fp16
__device__ __half g_Rh[(size_t)NS * MT];   // [k][n] fp16
__device__ __half g_Wh[(size_t)1024 * 128];// [k2][f] fp16
__device__ float  g_rinv[RT];

__device__ __forceinline__ void cp16(uint32_t dst, const void* src) {
    asm volatile("cp.async.cg.shared.global [%0], [%1], 16;\n" :: "r"(dst), "l"(src));
}
__device__ __forceinline__ void cp_commit() { asm volatile("cp.async.commit_group;\n" ::); }
__device__ __forceinline__ void cp_wait1()  { asm volatile("cp.async.wait_group 1;\n" ::); }

// ---------------- Kernel 1: LN + left/right projection (fp32 math) ---------
__global__ __launch_bounds__(256) void ln_proj_kernel(
    const float* __restrict__ act, const float* __restrict__ mask,
    const float* __restrict__ gamma, const float* __restrict__ beta,
    const float* __restrict__ lw, const float* __restrict__ lb,
    const float* __restrict__ rw, const float* __restrict__ rb)
{
    extern __shared__ float sm[];
    float* xs    = sm;                 // [64][260]
    float* sW    = sm + 64 * 260;      // [256][64]
    float* smask = sW + 256 * 64;      // [64]
    const int tid  = threadIdx.x;
    const int warp = tid >> 5, lane = tid & 31;
    const int rbase = blockIdx.x * 64;

    for (int i = 0; i < 64; i++) {
        int idx = tid + i * 256;
        int k = idx >> 6, cc = idx & 63;
        sW[idx] = (cc < 32) ? lw[k * 32 + cc] : rw[k * 32 + (cc - 32)];
    }
    for (int rr = 0; rr < 8; rr++) {
        int lr = warp * 8 + rr;
        int r  = rbase + lr;
        const float* arow = act + (size_t)r * CM;
        float x[8], s = 0.f, s2 = 0.f;
        #pragma unroll
        for (int j = 0; j < 8; j++) { x[j] = arow[lane + 32 * j]; s += x[j]; s2 += x[j] * x[j]; }
        #pragma unroll
        for (int o = 16; o > 0; o >>= 1) {
            s  += __shfl_xor_sync(0xffffffffu, s,  o);
            s2 += __shfl_xor_sync(0xffffffffu, s2, o);
        }
        float mu = s * (1.f / 256.f);
        float rstd = rsqrtf(s2 * (1.f / 256.f) - mu * mu + 1e-5f);
        float m = mask[r];
        if (lane == 0) smask[lr] = m;
        #pragma unroll
        for (int j = 0; j < 8; j++) {
            int k = lane + 32 * j;
            xs[lr * 260 + k] = ((x[j] - mu) * rstd * gamma[k] + beta[k]) * m;
        }
    }
    __syncthreads();

    const int tr4 = (tid >> 4) * 4, tc4 = (tid & 15) * 4;
    float acc[4][4] = {};
    for (int k = 0; k < 256; k += 4) {
        float4 w0 = *(const float4*)(sW + (k + 0) * 64 + tc4);
        float4 w1 = *(const float4*)(sW + (k + 1) * 64 + tc4);
        float4 w2 = *(const float4*)(sW + (k + 2) * 64 + tc4);
        float4 w3 = *(const float4*)(sW + (k + 3) * 64 + tc4);
        #pragma unroll
        for (int i = 0; i < 4; i++) {
            float4 xv = *(const float4*)(xs + (tr4 + i) * 260 + k);
            acc[i][0] += xv.x * w0.x + xv.y * w1.x + xv.z * w2.x + xv.w * w3.x;
            acc[i][1] += xv.x * w0.y + xv.y * w1.y + xv.z * w2.y + xv.w * w3.y;
            acc[i][2] += xv.x * w0.z + xv.y * w1.z + xv.z * w2.z + xv.w * w3.z;
            acc[i][3] += xv.x * w0.w + xv.y * w1.w + xv.z * w2.w + xv.w * w3.w;
        }
    }
    float b0, b1, b2, b3;
    if (tc4 < 32) { b0 = lb[tc4]; b1 = lb[tc4+1]; b2 = lb[tc4+2]; b3 = lb[tc4+3]; }
    else { b0 = rb[tc4-32]; b1 = rb[tc4-31]; b2 = rb[tc4-30]; b3 = rb[tc4-29]; }
    #pragma unroll
    for (int i = 0; i < 4; i++) {
        int r = rbase + tr4 + i;
        int aa = r / NR, bb = r % NR;
        float m = smask[tr4 + i];
        __half2 h0 = __floats2half2_rn(acc[i][0] + m * b0, acc[i][1] + m * b1);
        __half2 h1 = __floats2half2_rn(acc[i][2] + m * b2, acc[i][3] + m * b3);
        __half2* dst;
        if (tc4 < 32) dst = (__half2*)(g_Lh + (size_t)aa * MT + bb * 32 + tc4);
        else          dst = (__half2*)(g_Rh + (size_t)aa * MT + bb * 32 + (tc4 - 32));
        dst[0] = h0; dst[1] = h1;
    }
}

// ---------------- Kernel 2: rinv = 1/(eps + mask^T mask) -------------------
__global__ __launch_bounds__(NR) void norm_kernel(const float* __restrict__ mask)
{
    int b = blockIdx.x, d = threadIdx.x;
    float s = 0.f;
    for (int a = 0; a < NS; a++) s += mask[a * NR + b] * mask[a * NR + d];
    g_rinv[b * NR + d] = 1.f / (1e-3f + s);
}

// ---------------- Kernel 2b: output_w -> fp16 ------------------------------
__global__ __launch_bounds__(512) void conv_w_kernel(const float* __restrict__ ow)
{
    int i = blockIdx.x * 512 + threadIdx.x;     // 131072 elems, grid 256
    g_Wh[i] = __float2half_rn(ow[i]);
}

// ---- pipelined stage loaders (512 threads) --------------------------------
// phase1 stage s at byte s*25600: A[32][136]h at 0, B[32][264]h at 8704
__device__ __forceinline__ void load_stage_LR(uint32_t smb, int tid, int ks, int s,
                                              int m0, int n0)
{
    uint32_t st = smb + (uint32_t)s * 25600u;
    int k0 = ks * 32;
    {
        int kk = tid >> 4, c = tid & 15;            // 512 cp16 (A)
        cp16(st + (uint32_t)(kk * 272 + c * 16),
             g_Lh + (size_t)(k0 + kk) * MT + m0 + c * 8);
    }
    #pragma unroll
    for (int i = 0; i < 2; i++) {                   // 1024 cp16 (B)
        int idx = tid + i * 512;
        int kk = idx >> 5, c = idx & 31;
        cp16(st + 8704u + (uint32_t)(kk * 528 + c * 16),
             g_Rh + (size_t)(k0 + kk) * MT + n0 + c * 8);
    }
}

// phase2 W stage s at byte RB + s*17408; group g at +g*8704: [32][136]h
#define RB 66048u
__device__ __forceinline__ void load_stage_W2(uint32_t smb, int tid, int i_next, int s)
{
    uint32_t aW = smb + RB + (uint32_t)s * 17408u;
    #pragma unroll
    for (int g = 0; g < 2; g++) {
        int k0 = (g * 16 + i_next) * 32;
        int kk = tid >> 4, c = tid & 15;            // 512 cp16 per group
        cp16(aW + (uint32_t)(g * 8704 + kk * 272 + c * 16),
             g_Wh + (size_t)(k0 + kk) * 128 + c * 8);
    }
}

// ---------------- Kernel 3: FUSED fp16  inter = L^T R ; out = rinv*(.@W)+ob
// 512 threads. Mainloop 4x4 warp grid (32x64/warp), K=512, frags 16x16x16.
// Phase 2: sI[32][1032] half; 2-way K-split, 2x4 over 32x128.
// smem bytes: sI at 0 (66048); scratch/W/partials region at RB (34816).
__global__ __launch_bounds__(512) void gemm_fused_kernel(
    const float* __restrict__ ob, float* __restrict__ out)
{
    extern __shared__ char smraw[];
    __half* smh = (__half*)smraw;
    const int tid  = threadIdx.x;
    const int warp = tid >> 5, lane = tid & 31;
    const int wm = warp >> 2, wn = warp & 3;
    const int m0 = blockIdx.y * 128, n0 = blockIdx.x * 256;
    const uint32_t smb = (uint32_t)__cvta_generic_to_shared(smraw);

    wmma::fragment<wmma::accumulator, 16, 16, 16, float> c[2][4];
    #pragma unroll
    for (int i = 0; i < 2; i++)
        #pragma unroll
        for (int j = 0; j < 4; j++) wmma::fill_fragment(c[i][j], 0.0f);

    // ---- mainloop: double-buffered cp.async, 16 k-chunks of 32 ----
    load_stage_LR(smb, tid, 0, 0, m0, n0);
    cp_commit();
    for (int ks = 0; ks < 16; ks++) {
        int s = ks & 1;
        if (ks + 1 < 16) load_stage_LR(smb, tid, ks + 1, s ^ 1, m0, n0);
        cp_commit();
        cp_wait1();
        __syncthreads();
        __half* sA = (__half*)(smraw + s * 25600);        // [32][136]
        __half* sB = (__half*)(smraw + s * 25600 + 8704); // [32][264]
        #pragma unroll
        for (int kk = 0; kk < 32; kk += 16) {
            wmma::fragment<wmma::matrix_a, 16, 16, 16, half, wmma::col_major> af[2];
            wmma::fragment<wmma::matrix_b, 16, 16, 16, half, wmma::row_major> bf[4];
            #pragma unroll
            for (int i = 0; i < 2; i++)
                wmma::load_matrix_sync(af[i], sA + kk * 136 + wm * 32 + i * 16, 136);
            #pragma unroll
            for (int j = 0; j < 4; j++)
                wmma::load_matrix_sync(bf[j], sB + kk * 264 + wn * 64 + j * 16, 264);
            #pragma unroll
            for (int i = 0; i < 2; i++)
                #pragma unroll
                for (int j = 0; j < 4; j++)
                    wmma::mma_sync(c[i][j], af[i], bf[j], c[i][j]);
        }
        __syncthreads();
    }

    // ---- convert accumulators -> sI[r][(c*32+e)] half, via per-warp scratch
    __half* sI = smh;                          // [32][1032]
    float*  scr = (float*)(smraw + RB) + warp * 256;   // 16x16 per warp
    #pragma unroll
    for (int i = 0; i < 2; i++)
        #pragma unroll
        for (int j = 0; j < 4; j++) {
            int ml = wm * 32 + i * 16, nl = wn * 64 + j * 16;
            int r  = (ml >> 5) * 8 + (nl >> 5);
            int cl = ml & 31, el = nl & 31;
            wmma::store_matrix_sync(scr, c[i][j], 16, wmma::mem_row_major);
            __syncwarp();
            int row = lane >> 1, h8 = (lane & 1) * 8;
            const float* sr = scr + row * 16 + h8;
            uint32_t p[4];
            #pragma unroll
            for (int t = 0; t < 4; t++) {
                __half2 hh = __floats2half2_rn(sr[2*t], sr[2*t+1]);
                p[t] = *(uint32_t*)&hh;
            }
            *(uint4*)(sI + (size_t)r * 1032 + (cl + row) * 32 + el + h8) =
                make_uint4(p[0], p[1], p[2], p[3]);
            __syncwarp();
        }
    __syncthreads();

    // ---- W-contraction, 2-way K-split: [32 x 1024] @ [1024 x 128] ---------
    const int kg = warp >> 3;
    const int ws = warp & 7;
    const int pm = ws >> 2, pn = ws & 3;

    wmma::fragment<wmma::accumulator, 16, 16, 16, float> o[2];
    wmma::fill_fragment(o[0], 0.0f);
    wmma::fill_fragment(o[1], 0.0f);

    load_stage_W2(smb, tid, 0, 0);
    cp_commit();
    for (int i = 0; i < 16; i++) {
        int s = i & 1;
        if (i + 1 < 16) load_stage_W2(smb, tid, i + 1, s ^ 1);
        cp_commit();
        cp_wait1();
        __syncthreads();
        __half* sWc = (__half*)(smraw + RB + s * 17408 + kg * 8704);  // [32][136]
        int kcol = (kg * 16 + i) * 32;
        #pragma unroll
        for (int kk = 0; kk < 32; kk += 16) {
            wmma::fragment<wmma::matrix_a, 16, 16, 16, half, wmma::row_major> af;
            wmma::load_matrix_sync(af, sI + (size_t)(pm * 16) * 1032 + kcol + kk, 1032);
            #pragma unroll
            for (int j = 0; j < 2; j++) {
                wmma::fragment<wmma::matrix_b, 16, 16, 16, half, wmma::row_major> bf;
                wmma::load_matrix_sync(bf, sWc + kk * 136 + pn * 32 + j * 16, 136);
                wmma::mma_sync(o[j], af, bf, o[j]);
            }
        }
        __syncthreads();
    }

    // ---- partials -> smem, reduce, scale by rinv, +bias, store ------------
    float* sO = (float*)(smraw + RB);          // [2][32][132]
    #pragma unroll
    for (int j = 0; j < 2; j++)
        wmma::store_matrix_sync(sO + kg * 4224 + (pm * 16) * 132 + pn * 32 + j * 16,
                                o[j], 132, wmma::mem_row_major);
    __syncthreads();

    const int b0 = blockIdx.y * 4, d0 = blockIdx.x * 8;
    #pragma unroll
    for (int it = 0; it < 2; it++) {
        int flat = tid + it * 512;           // 1024 float4s = 32x128
        int r = flat >> 5, fc = (flat & 31) << 2;
        float4 v0 = *(float4*)(sO + r * 132 + fc);
        float4 v1 = *(float4*)(sO + 4224 + r * 132 + fc);
        int orow  = (b0 + (r >> 3)) * NR + d0 + (r & 7);
        float rv  = g_rinv[orow];
        float4 bb = *(const float4*)(ob + fc);
        float4 w  = { (v0.x + v1.x) * rv + bb.x, (v0.y + v1.y) * rv + bb.y,
                      (v0.z + v1.z) * rv + bb.z, (v0.w + v1.w) * rv + bb.w };
        *(float4*)(out + (size_t)orow * 128 + fc) = w;
    }
}

// ---------------------------------------------------------------------------
extern "C" void kernel_launch(void* const* d_in, const int* in_sizes, int n_in,
                              void* d_out, int out_size)
{
    const float* act      = (const float*)d_in[0];
    const float* mask     = (const float*)d_in[1];
    const float* ln_scale = (const float*)d_in[2];
    const float* ln_off   = (const float*)d_in[3];
    const float* left_w   = (const float*)d_in[4];
    const float* left_b   = (const float*)d_in[5];
    const float* right_w  = (const float*)d_in[6];
    const float* right_b  = (const float*)d_in[7];
    const float* out_w    = (const float*)d_in[8];
    const float* out_b    = (const float*)d_in[9];
    float* out = (float*)d_out;

    const int smem1 = (64 * 260 + 256 * 64 + 64) * 4;    // 132352
    const int smem3 = 66048 + 34816;                     // 100864
    cudaFuncSetAttribute(ln_proj_kernel,    cudaFuncAttributeMaxDynamicSharedMemorySize, smem1);
    cudaFuncSetAttribute(gemm_fused_kernel, cudaFuncAttributeMaxDynamicSharedMemorySize, smem3);

    ln_proj_kernel<<<(NS * NR) / 64, 256, smem1>>>(act, mask, ln_scale, ln_off,
                                                   left_w, left_b, right_w, right_b);
    norm_kernel<<<NR, NR>>>(mask);
    conv_w_kernel<<<256, 512>>>(out_w);
    gemm_fused_kernel<<<dim3(MT / 256, MT / 128), 512, smem3>>>(out_b, out);
}